// round 4
// baseline (speedup 1.0000x reference)
#include <cuda_runtime.h>
#include <cstdint>

#define B   64
#define C   64
#define NN  16384
#define ITE 20
#define RNK 3
#define CH  32                 // G-partial chunks per band
#define CPC (NN/CH)            // 512 cols per chunk
#define SUB 128                // subtile columns
#define NSUBT (CPC/SUB)        // 4
#define NSWEEP 12
#define UVN ((size_t)B*C*NN)   // 67,108,864
#define INV_CNT (1.0f/67108864.0f)   // 2^-26, exact

// ---------------- device scratch (no allocation allowed) ----------------
__device__ float g_L[(size_t)B*C*NN];          // 256 MB  working L
__device__ float g_Gpart[(size_t)CH*B*C*C];    // 32 MB   SYRK partials
__device__ float g_Ur[B*C*RNK];                // top-3 eigvecs per band
__device__ float g_losspart[B*CH*2];           // per-block (lossF, loss)
__device__ float g_wpart[8192];
__device__ float g_rho0;

// ---------------- packed f32x2 helpers (sm_103a) ----------------
// f32x2 ops are typed .b64 in PTX — use uint64_t / "l" (%rd regs), matching
// ptx_helpers.cuh's MUL_F32X2/ADD_F32X2 pattern.
__device__ __forceinline__ uint64_t pk2(float a, float b){
    uint64_t r; asm("mov.b64 %0, {%1,%2};" : "=l"(r) : "f"(a), "f"(b)); return r;
}
__device__ __forceinline__ void fma2(uint64_t& acc, uint64_t a, uint64_t b){
    asm("fma.rn.f32x2 %0, %1, %2, %0;" : "+l"(acc) : "l"(a), "l"(b));
}
__device__ __forceinline__ float2 upk2(uint64_t a){
    float2 r; asm("mov.b64 {%0,%1}, %2;" : "=f"(r.x), "=f"(r.y) : "l"(a)); return r;
}

// ---------------- mean(W) ----------------
__global__ void __launch_bounds__(256) k_wsum(const float* __restrict__ W){
    __shared__ float sred[8];
    const int tid = threadIdx.x;
    const size_t base = (size_t)blockIdx.x * 8192;
    float s = 0.f;
    #pragma unroll 4
    for (int k = 0; k < 32; k++) s += W[base + (size_t)k*256 + tid];
    for (int o = 16; o > 0; o >>= 1) s += __shfl_down_sync(0xffffffffu, s, o);
    if ((tid & 31) == 0) sred[tid >> 5] = s;
    __syncthreads();
    if (tid == 0){
        float a = 0.f;
        for (int w = 0; w < 8; w++) a += sred[w];
        g_wpart[blockIdx.x] = a;
    }
}

__global__ void __launch_bounds__(256) k_wred(){
    __shared__ float sred[8];
    const int tid = threadIdx.x;
    float s = 0.f;
    for (int k = 0; k < 32; k++) s += g_wpart[tid + k*256];
    for (int o = 16; o > 0; o >>= 1) s += __shfl_down_sync(0xffffffffu, s, o);
    if ((tid & 31) == 0) sred[tid >> 5] = s;
    __syncthreads();
    if (tid == 0){
        float a = 0.f;
        for (int w = 0; w < 8; w++) a += sred[w];
        g_rho0 = 0.5f * (a * INV_CNT);
    }
}

// ---------------- fused main kernel ----------------
// Per (band, chunk): for 4 subtiles of 128 cols:
//   load L tile -> smem; UtL coeffs; elementwise (UV, losses, L_new, write-back);
//   SYRK-accumulate next-G partials from L_new tile via f32x2 FMAs.
__global__ void __launch_bounds__(256) k_main(const float* __restrict__ x,
                                              const float* __restrict__ W,
                                              float* __restrict__ out,
                                              int t, int init)
{
    __shared__ float Ls[C][132];       // padded stride: av broadcast, bv conflict-free
    __shared__ float cs[RNK][SUB];
    __shared__ float sUr[C*RNK];
    __shared__ float sred[16];

    const int band  = blockIdx.y;
    const int chunk = blockIdx.x;
    const int tid   = threadIdx.x;
    const size_t baseBand = (size_t)band * C * NN;
    const int col0 = chunk * CPC;

    const float* Lsrc = (init || t == 0) ? x : g_L;
    const bool doG  = (init != 0) || (t < ITE-1);
    const bool last = (!init) && (t == ITE-1);

    if (!init && tid < C*RNK) sUr[tid] = g_Ur[band*(C*RNK) + tid];

    float rho = g_rho0;
    for (int i = 0; i < t; i++) rho *= 1.05f;   // replicate f32 repeated multiply

    uint64_t acc2[4][4];
    #pragma unroll
    for (int i = 0; i < 4; i++)
        #pragma unroll
        for (int j = 0; j < 4; j++) acc2[i][j] = pk2(0.f, 0.f);

    float lF = 0.f, lU = 0.f;
    const int tx = tid & 15, ty = tid >> 4;

    for (int s = 0; s < NSUBT; s++) {
        const int nb = col0 + s*SUB;

        // ---- load 64x128 L subtile (float4, coalesced) ----
        {
            const float4* L4 = (const float4*)Lsrc;
            #pragma unroll
            for (int k = 0; k < 8; k++){
                int idx = k*256 + tid;             // 0..2047 float4s
                int ch = idx >> 5, n4 = idx & 31;
                float4 v = L4[(baseBand + (size_t)ch*NN + nb)/4 + n4];
                *(float4*)&Ls[ch][n4*4] = v;
            }
        }
        __syncthreads();

        if (!init) {
            // ---- UtL coefficients: cs[r][n] = sum_ch Ur[ch][r]*L[ch][n] ----
            if (tid < SUB) {
                float c0 = 0.f, c1 = 0.f, c2 = 0.f;
                #pragma unroll
                for (int ch = 0; ch < C; ch++){
                    float l = Ls[ch][tid];
                    c0 += sUr[ch*3+0]*l;
                    c1 += sUr[ch*3+1]*l;
                    c2 += sUr[ch*3+2]*l;
                }
                cs[0][tid] = c0; cs[1][tid] = c1; cs[2][tid] = c2;
            }
            __syncthreads();

            // ---- elementwise: UV, losses, L_new ----
            const float4* x4  = (const float4*)x;
            const float4* W4  = (const float4*)W;
            float4* o4  = (float4*)out;
            float4* gl4 = (float4*)g_L;
            #pragma unroll
            for (int k = 0; k < 8; k++){
                int idx = k*256 + tid;
                int ch = idx >> 5, n4 = idx & 31;
                int n = n4*4;
                size_t g4 = (baseBand + (size_t)ch*NN + nb)/4 + n4;
                float4 xv = x4[g4], wv = W4[g4];
                float u0 = sUr[ch*3+0], u1 = sUr[ch*3+1], u2 = sUr[ch*3+2];
                float4 uv;
                uv.x = u0*cs[0][n+0] + u1*cs[1][n+0] + u2*cs[2][n+0];
                uv.y = u0*cs[0][n+1] + u1*cs[1][n+1] + u2*cs[2][n+1];
                uv.z = u0*cs[0][n+2] + u1*cs[1][n+2] + u2*cs[2][n+2];
                uv.w = u0*cs[0][n+3] + u1*cs[1][n+3] + u2*cs[2][n+3];
                lU += uv.x*uv.x + uv.y*uv.y + uv.z*uv.z + uv.w*uv.w;
                float da = uv.x - xv.x, db = uv.y - xv.y;
                float dc = uv.z - xv.z, dd = uv.w - xv.w;
                lF += wv.x*da*da + wv.y*db*db + wv.z*dc*dc + wv.w*dd*dd;
                if (last) {
                    o4[g4] = uv;
                } else {
                    float4 ln;
                    float m;
                    m = rho/(wv.x+rho); ln.x = (1.f-m)*xv.x + m*uv.x;
                    m = rho/(wv.y+rho); ln.y = (1.f-m)*xv.y + m*uv.y;
                    m = rho/(wv.z+rho); ln.z = (1.f-m)*xv.z + m*uv.z;
                    m = rho/(wv.w+rho); ln.w = (1.f-m)*xv.w + m*uv.w;
                    gl4[g4] = ln;
                    *(float4*)&Ls[ch][n] = ln;   // SYRK uses L_new
                }
            }
            __syncthreads();
        }

        // ---- SYRK accumulate: G += tile * tile^T (f32x2, n-pair packed) ----
        if (doG) {
            #pragma unroll 4
            for (int n = 0; n < SUB; n += 4){
                float4 av[4], bv[4];
                #pragma unroll
                for (int i = 0; i < 4; i++) av[i] = *(const float4*)&Ls[ty+16*i][n];
                #pragma unroll
                for (int j = 0; j < 4; j++) bv[j] = *(const float4*)&Ls[tx+16*j][n];
                uint64_t a01[4], a23[4], b01[4], b23[4];
                #pragma unroll
                for (int i = 0; i < 4; i++){ a01[i] = pk2(av[i].x, av[i].y); a23[i] = pk2(av[i].z, av[i].w); }
                #pragma unroll
                for (int j = 0; j < 4; j++){ b01[j] = pk2(bv[j].x, bv[j].y); b23[j] = pk2(bv[j].z, bv[j].w); }
                #pragma unroll
                for (int i = 0; i < 4; i++)
                    #pragma unroll
                    for (int j = 0; j < 4; j++){
                        fma2(acc2[i][j], a01[i], b01[j]);
                        fma2(acc2[i][j], a23[i], b23[j]);
                    }
            }
        }
        __syncthreads();
    }

    if (doG) {
        float* gp = &g_Gpart[((size_t)chunk*B + band)*(C*C)];
        #pragma unroll
        for (int i = 0; i < 4; i++)
            #pragma unroll
            for (int j = 0; j < 4; j++){
                float2 u = upk2(acc2[i][j]);
                gp[(ty+16*i)*C + (tx+16*j)] = u.x + u.y;
            }
    }

    if (!init) {
        for (int o = 16; o > 0; o >>= 1){
            lF += __shfl_down_sync(0xffffffffu, lF, o);
            lU += __shfl_down_sync(0xffffffffu, lU, o);
        }
        if ((tid & 31) == 0){ sred[tid>>5] = lF; sred[8 + (tid>>5)] = lU; }
        __syncthreads();
        if (tid == 0){
            float a = 0.f, b2 = 0.f;
            for (int w = 0; w < 8; w++){ a += sred[w]; b2 += sred[8+w]; }
            g_losspart[(band*CH + chunk)*2 + 0] = a;
            g_losspart[(band*CH + chunk)*2 + 1] = b2;
        }
    }
}

// ---------------- eigensolver: reduce G partials + parallel Jacobi ----------------
__global__ void __launch_bounds__(256) k_eig()
{
    __shared__ float sG[C][65];
    __shared__ float sV[C][65];
    __shared__ float rc[32], rs[32];
    __shared__ int   rp[32], rq[32];
    __shared__ int   topi[RNK];
    const int band = blockIdx.x;
    const int tid  = threadIdx.x;

    for (int e = tid; e < C*C; e += 256){
        float s = 0.f;
        for (int c2 = 0; c2 < CH; c2++)
            s += g_Gpart[((size_t)c2*B + band)*(C*C) + e];
        sG[e>>6][e&63] = s;
        sV[e>>6][e&63] = ((e>>6) == (e&63)) ? 1.f : 0.f;
    }
    __syncthreads();

    for (int sweep = 0; sweep < NSWEEP; sweep++){
        for (int r = 0; r < 63; r++){
            if (tid < 32){
                int p, q;
                if (tid == 0){ p = 63; q = r % 63; }
                else { p = (r + tid) % 63; q = (r + 63 - tid) % 63; }
                if (p > q){ int tmp = p; p = q; q = tmp; }
                float app = sG[p][p], aqq = sG[q][q], apq = sG[p][q];
                float c = 1.f, sn = 0.f;
                if (fabsf(apq) > 1e-20f){
                    float tau = (aqq - app) / (2.f * apq);
                    float tt  = ((tau >= 0.f) ? 1.f : -1.f) / (fabsf(tau) + sqrtf(1.f + tau*tau));
                    c  = 1.f / sqrtf(1.f + tt*tt);
                    sn = tt * c;
                }
                rc[tid] = c; rs[tid] = sn; rp[tid] = p; rq[tid] = q;
            }
            __syncthreads();
            #pragma unroll
            for (int k8 = 0; k8 < 8; k8++){            // rows: G <- J^T G
                int idx = k8*256 + tid;
                int k = idx >> 6, j = idx & 63;
                int p = rp[k], q = rq[k];
                float c = rc[k], sn = rs[k];
                float gp = sG[p][j], gq = sG[q][j];
                sG[p][j] = c*gp - sn*gq;
                sG[q][j] = sn*gp + c*gq;
            }
            __syncthreads();
            #pragma unroll
            for (int k8 = 0; k8 < 8; k8++){            // cols: (.)J  and V <- V J
                int idx = k8*256 + tid;
                int k = idx >> 6, i = idx & 63;
                int p = rp[k], q = rq[k];
                float c = rc[k], sn = rs[k];
                float gp = sG[i][p], gq = sG[i][q];
                sG[i][p] = c*gp - sn*gq;
                sG[i][q] = sn*gp + c*gq;
                float vp = sV[i][p], vq = sV[i][q];
                sV[i][p] = c*vp - sn*vq;
                sV[i][q] = sn*vp + c*vq;
            }
            __syncthreads();
        }
    }

    if (tid == 0){
        unsigned long long used = 0ull;
        for (int rr = 0; rr < RNK; rr++){
            float best = -3.4e38f; int bi = 0;
            for (int i2 = 0; i2 < C; i2++){
                if (used & (1ull << i2)) continue;
                float d = sG[i2][i2];
                if (d > best){ best = d; bi = i2; }
            }
            used |= (1ull << bi);
            topi[rr] = bi;
        }
    }
    __syncthreads();
    for (int idx = tid; idx < C*RNK; idx += 256){
        int ch = idx / 3, rr = idx % 3;
        g_Ur[band*(C*RNK) + idx] = sV[ch][topi[rr]];
    }
}

// ---------------- loss reduction ----------------
__global__ void __launch_bounds__(256) k_loss(float* __restrict__ out, int t){
    __shared__ float sF[8], sU[8];
    const int tid = threadIdx.x;
    float f = 0.f, u = 0.f;
    #pragma unroll
    for (int k = 0; k < 8; k++){
        int idx = tid + k*256;
        f += g_losspart[idx*2 + 0];
        u += g_losspart[idx*2 + 1];
    }
    for (int o = 16; o > 0; o >>= 1){
        f += __shfl_down_sync(0xffffffffu, f, o);
        u += __shfl_down_sync(0xffffffffu, u, o);
    }
    if ((tid & 31) == 0){ sF[tid>>5] = f; sU[tid>>5] = u; }
    __syncthreads();
    if (tid == 0){
        float a = 0.f, b2 = 0.f;
        for (int w = 0; w < 8; w++){ a += sF[w]; b2 += sU[w]; }
        out[UVN + t]        = a  * INV_CNT;   // loss_F
        out[UVN + ITE + t]  = b2 * INV_CNT;   // loss
    }
}

// ---------------- launch ----------------
extern "C" void kernel_launch(void* const* d_in, const int* in_sizes, int n_in,
                              void* d_out, int out_size)
{
    const float* x = (const float*)d_in[0];
    const float* W = (const float*)d_in[1];
    float* out = (float*)d_out;

    k_wsum<<<8192, 256>>>(W);
    k_wred<<<1, 256>>>();
    k_main<<<dim3(CH, B), 256>>>(x, W, out, 0, 1);      // G partials from L0 = x
    for (int t = 0; t < ITE; t++){
        k_eig<<<B, 256>>>();                            // Ur_t from G(L_t)
        k_main<<<dim3(CH, B), 256>>>(x, W, out, t, 0);  // UV_t, losses, L_{t+1}, G(L_{t+1})
        k_loss<<<1, 256>>>(out, t);
    }
}

// round 14
// speedup vs baseline: 1.6948x; 1.6948x over previous
#include <cuda_runtime.h>
#include <cstdint>

#define B   64
#define C   64
#define NN  16384
#define ITE 20
#define RNK 3
#define CH  32                 // G-partial chunks per band
#define CPC (NN/CH)            // 512 cols per chunk
#define SUB 128                // subtile columns
#define NSUBT (CPC/SUB)        // 4
#define NSWEEP 8
#define UVN ((size_t)B*C*NN)   // 67,108,864
#define INV_CNT (1.0f/67108864.0f)   // 2^-26, exact

// ---------------- device scratch (no allocation allowed) ----------------
__device__ float g_L[(size_t)B*C*NN];          // 256 MB  working L
__device__ float g_Gpart[(size_t)CH*B*C*C];    // 32 MB   SYRK partials
__device__ float g_Ur[B*C*RNK];                // top-3 eigvecs per band
__device__ float g_losspart[B*CH*2];           // per-block (lossF, loss)
__device__ float g_wpart[8192];
__device__ float g_rho0;

// ---------------- packed f32x2 helpers (sm_103a) ----------------
__device__ __forceinline__ uint64_t pk2(float a, float b){
    uint64_t r; asm("mov.b64 %0, {%1,%2};" : "=l"(r) : "f"(a), "f"(b)); return r;
}
__device__ __forceinline__ void fma2(uint64_t& acc, uint64_t a, uint64_t b){
    asm("fma.rn.f32x2 %0, %1, %2, %0;" : "+l"(acc) : "l"(a), "l"(b));
}
__device__ __forceinline__ float2 upk2(uint64_t a){
    float2 r; asm("mov.b64 {%0,%1}, %2;" : "=f"(r.x), "=f"(r.y) : "l"(a)); return r;
}

// ---------------- mean(W) ----------------
__global__ void __launch_bounds__(256) k_wsum(const float* __restrict__ W){
    __shared__ float sred[8];
    const int tid = threadIdx.x;
    const size_t base = (size_t)blockIdx.x * 8192;
    float s = 0.f;
    #pragma unroll 4
    for (int k = 0; k < 32; k++) s += W[base + (size_t)k*256 + tid];
    for (int o = 16; o > 0; o >>= 1) s += __shfl_down_sync(0xffffffffu, s, o);
    if ((tid & 31) == 0) sred[tid >> 5] = s;
    __syncthreads();
    if (tid == 0){
        float a = 0.f;
        for (int w = 0; w < 8; w++) a += sred[w];
        g_wpart[blockIdx.x] = a;
    }
}

__global__ void __launch_bounds__(256) k_wred(){
    __shared__ float sred[8];
    const int tid = threadIdx.x;
    float s = 0.f;
    for (int k = 0; k < 32; k++) s += g_wpart[tid + k*256];
    for (int o = 16; o > 0; o >>= 1) s += __shfl_down_sync(0xffffffffu, s, o);
    if ((tid & 31) == 0) sred[tid >> 5] = s;
    __syncthreads();
    if (tid == 0){
        float a = 0.f;
        for (int w = 0; w < 8; w++) a += sred[w];
        g_rho0 = 0.5f * (a * INV_CNT);
    }
}

// ---------------- fused main kernel ----------------
__global__ void __launch_bounds__(256) k_main(const float* __restrict__ x,
                                              const float* __restrict__ W,
                                              float* __restrict__ out,
                                              int t, int init)
{
    __shared__ float Ls[C][132];       // padded stride: av broadcast, bv conflict-free
    __shared__ float cs[RNK][SUB];
    __shared__ float sUr[C*RNK];
    __shared__ float sred[16];

    const int band  = blockIdx.y;
    const int chunk = blockIdx.x;
    const int tid   = threadIdx.x;
    const size_t baseBand = (size_t)band * C * NN;
    const int col0 = chunk * CPC;

    const float* Lsrc = (init || t == 0) ? x : g_L;
    const bool doG  = (init != 0) || (t < ITE-1);
    const bool last = (!init) && (t == ITE-1);

    if (!init && tid < C*RNK) sUr[tid] = g_Ur[band*(C*RNK) + tid];

    float rho = g_rho0;
    for (int i = 0; i < t; i++) rho *= 1.05f;   // replicate f32 repeated multiply

    uint64_t acc2[4][4];
    #pragma unroll
    for (int i = 0; i < 4; i++)
        #pragma unroll
        for (int j = 0; j < 4; j++) acc2[i][j] = pk2(0.f, 0.f);

    float lF = 0.f, lU = 0.f;
    const int tx = tid & 15, ty = tid >> 4;

    for (int s = 0; s < NSUBT; s++) {
        const int nb = col0 + s*SUB;

        // ---- load 64x128 L subtile (float4, coalesced) ----
        {
            const float4* L4 = (const float4*)Lsrc;
            #pragma unroll
            for (int k = 0; k < 8; k++){
                int idx = k*256 + tid;             // 0..2047 float4s
                int ch = idx >> 5, n4 = idx & 31;
                float4 v = L4[(baseBand + (size_t)ch*NN + nb)/4 + n4];
                *(float4*)&Ls[ch][n4*4] = v;
            }
        }
        __syncthreads();

        if (!init) {
            // ---- UtL coefficients: cs[r][n] = sum_ch Ur[ch][r]*L[ch][n] ----
            if (tid < SUB) {
                float c0 = 0.f, c1 = 0.f, c2 = 0.f;
                #pragma unroll
                for (int ch = 0; ch < C; ch++){
                    float l = Ls[ch][tid];
                    c0 += sUr[ch*3+0]*l;
                    c1 += sUr[ch*3+1]*l;
                    c2 += sUr[ch*3+2]*l;
                }
                cs[0][tid] = c0; cs[1][tid] = c1; cs[2][tid] = c2;
            }
            __syncthreads();

            // ---- elementwise: UV, losses, L_new (fast division) ----
            const float4* x4  = (const float4*)x;
            const float4* W4  = (const float4*)W;
            float4* o4  = (float4*)out;
            float4* gl4 = (float4*)g_L;
            #pragma unroll
            for (int k = 0; k < 8; k++){
                int idx = k*256 + tid;
                int ch = idx >> 5, n4 = idx & 31;
                int n = n4*4;
                size_t g4 = (baseBand + (size_t)ch*NN + nb)/4 + n4;
                float4 xv = x4[g4], wv = W4[g4];
                float u0 = sUr[ch*3+0], u1 = sUr[ch*3+1], u2 = sUr[ch*3+2];
                float4 uv;
                uv.x = u0*cs[0][n+0] + u1*cs[1][n+0] + u2*cs[2][n+0];
                uv.y = u0*cs[0][n+1] + u1*cs[1][n+1] + u2*cs[2][n+1];
                uv.z = u0*cs[0][n+2] + u1*cs[1][n+2] + u2*cs[2][n+2];
                uv.w = u0*cs[0][n+3] + u1*cs[1][n+3] + u2*cs[2][n+3];
                lU += uv.x*uv.x + uv.y*uv.y + uv.z*uv.z + uv.w*uv.w;
                float da = uv.x - xv.x, db = uv.y - xv.y;
                float dc = uv.z - xv.z, dd = uv.w - xv.w;
                lF += wv.x*da*da + wv.y*db*db + wv.z*dc*dc + wv.w*dd*dd;
                if (last) {
                    o4[g4] = uv;
                } else {
                    float4 ln;
                    float m;
                    m = __fdividef(rho, wv.x + rho); ln.x = fmaf(m, da, xv.x);
                    m = __fdividef(rho, wv.y + rho); ln.y = fmaf(m, db, xv.y);
                    m = __fdividef(rho, wv.z + rho); ln.z = fmaf(m, dc, xv.z);
                    m = __fdividef(rho, wv.w + rho); ln.w = fmaf(m, dd, xv.w);
                    gl4[g4] = ln;
                    *(float4*)&Ls[ch][n] = ln;   // SYRK uses L_new
                }
            }
            __syncthreads();
        }

        // ---- SYRK accumulate: G += tile * tile^T (f32x2, n-pair packed) ----
        if (doG) {
            #pragma unroll 4
            for (int n = 0; n < SUB; n += 4){
                float4 av[4], bv[4];
                #pragma unroll
                for (int i = 0; i < 4; i++) av[i] = *(const float4*)&Ls[ty+16*i][n];
                #pragma unroll
                for (int j = 0; j < 4; j++) bv[j] = *(const float4*)&Ls[tx+16*j][n];
                uint64_t a01[4], a23[4], b01[4], b23[4];
                #pragma unroll
                for (int i = 0; i < 4; i++){ a01[i] = pk2(av[i].x, av[i].y); a23[i] = pk2(av[i].z, av[i].w); }
                #pragma unroll
                for (int j = 0; j < 4; j++){ b01[j] = pk2(bv[j].x, bv[j].y); b23[j] = pk2(bv[j].z, bv[j].w); }
                #pragma unroll
                for (int i = 0; i < 4; i++)
                    #pragma unroll
                    for (int j = 0; j < 4; j++){
                        fma2(acc2[i][j], a01[i], b01[j]);
                        fma2(acc2[i][j], a23[i], b23[j]);
                    }
            }
        }
        __syncthreads();
    }

    if (doG) {
        float* gp = &g_Gpart[((size_t)chunk*B + band)*(C*C)];
        #pragma unroll
        for (int i = 0; i < 4; i++)
            #pragma unroll
            for (int j = 0; j < 4; j++){
                float2 u = upk2(acc2[i][j]);
                gp[(ty+16*i)*C + (tx+16*j)] = u.x + u.y;
            }
    }

    if (!init) {
        for (int o = 16; o > 0; o >>= 1){
            lF += __shfl_down_sync(0xffffffffu, lF, o);
            lU += __shfl_down_sync(0xffffffffu, lU, o);
        }
        if ((tid & 31) == 0){ sred[tid>>5] = lF; sred[8 + (tid>>5)] = lU; }
        __syncthreads();
        if (tid == 0){
            float a = 0.f, b2 = 0.f;
            for (int w = 0; w < 8; w++){ a += sred[w]; b2 += sred[8+w]; }
            g_losspart[(band*CH + chunk)*2 + 0] = a;
            g_losspart[(band*CH + chunk)*2 + 1] = b2;
        }
    }
}

// ---------------- eigensolver: reduce G partials + parallel Jacobi ----------------
// 512 threads: halves per-thread work in the smem row/col phases (the
// serial-path cost), rotation phase unchanged (tid<32).
__global__ void __launch_bounds__(512) k_eig()
{
    __shared__ float sG[C][65];
    __shared__ float sV[C][65];
    __shared__ float rc[32], rs[32];
    __shared__ int   rp[32], rq[32];
    __shared__ int   topi[RNK];
    const int band = blockIdx.x;
    const int tid  = threadIdx.x;

    for (int e = tid; e < C*C; e += 512){
        float s = 0.f;
        for (int c2 = 0; c2 < CH; c2++)
            s += g_Gpart[((size_t)c2*B + band)*(C*C) + e];
        sG[e>>6][e&63] = s;
        sV[e>>6][e&63] = ((e>>6) == (e&63)) ? 1.f : 0.f;
    }
    __syncthreads();

    for (int sweep = 0; sweep < NSWEEP; sweep++){
        for (int r = 0; r < 63; r++){
            if (tid < 32){
                int p, q;
                if (tid == 0){ p = 63; q = r % 63; }
                else { p = (r + tid) % 63; q = (r + 63 - tid) % 63; }
                if (p > q){ int tmp = p; p = q; q = tmp; }
                float app = sG[p][p], aqq = sG[q][q], apq = sG[p][q];
                float c = 1.f, sn = 0.f;
                // relative guard keeps tau^2 finite for the fast-math path;
                // relatively-tiny apq entries are already converged
                if (fabsf(apq) > 1e-12f*(fabsf(app)+fabsf(aqq)) + 1e-30f){
                    float tau = __fdividef(aqq - app, 2.f * apq);
                    float s1  = 1.f + tau*tau;
                    float sq  = s1 * rsqrtf(s1);            // ~sqrt(1+tau^2)
                    float tt  = __fdividef((tau >= 0.f) ? 1.f : -1.f,
                                           fabsf(tau) + sq);
                    c  = rsqrtf(1.f + tt*tt);
                    sn = tt * c;
                }
                rc[tid] = c; rs[tid] = sn; rp[tid] = p; rq[tid] = q;
            }
            __syncthreads();
            #pragma unroll
            for (int k4 = 0; k4 < 4; k4++){            // rows: G <- J^T G
                int idx = k4*512 + tid;
                int k = idx >> 6, j = idx & 63;
                int p = rp[k], q = rq[k];
                float c = rc[k], sn = rs[k];
                float gp = sG[p][j], gq = sG[q][j];
                sG[p][j] = c*gp - sn*gq;
                sG[q][j] = sn*gp + c*gq;
            }
            __syncthreads();
            #pragma unroll
            for (int k4 = 0; k4 < 4; k4++){            // cols: (.)J  and V <- V J
                int idx = k4*512 + tid;
                int k = idx >> 6, i = idx & 63;
                int p = rp[k], q = rq[k];
                float c = rc[k], sn = rs[k];
                float gp = sG[i][p], gq = sG[i][q];
                sG[i][p] = c*gp - sn*gq;
                sG[i][q] = sn*gp + c*gq;
                float vp = sV[i][p], vq = sV[i][q];
                sV[i][p] = c*vp - sn*vq;
                sV[i][q] = sn*vp + c*vq;
            }
            __syncthreads();
        }
    }

    if (tid == 0){
        unsigned long long used = 0ull;
        for (int rr = 0; rr < RNK; rr++){
            float best = -3.4e38f; int bi = 0;
            for (int i2 = 0; i2 < C; i2++){
                if (used & (1ull << i2)) continue;
                float d = sG[i2][i2];
                if (d > best){ best = d; bi = i2; }
            }
            used |= (1ull << bi);
            topi[rr] = bi;
        }
    }
    __syncthreads();
    for (int idx = tid; idx < C*RNK; idx += 512){
        int ch = idx / 3, rr = idx % 3;
        g_Ur[band*(C*RNK) + idx] = sV[ch][topi[rr]];
    }
}

// ---------------- loss reduction ----------------
__global__ void __launch_bounds__(256) k_loss(float* __restrict__ out, int t){
    __shared__ float sF[8], sU[8];
    const int tid = threadIdx.x;
    float f = 0.f, u = 0.f;
    #pragma unroll
    for (int k = 0; k < 8; k++){
        int idx = tid + k*256;
        f += g_losspart[idx*2 + 0];
        u += g_losspart[idx*2 + 1];
    }
    for (int o = 16; o > 0; o >>= 1){
        f += __shfl_down_sync(0xffffffffu, f, o);
        u += __shfl_down_sync(0xffffffffu, u, o);
    }
    if ((tid & 31) == 0){ sF[tid>>5] = f; sU[tid>>5] = u; }
    __syncthreads();
    if (tid == 0){
        float a = 0.f, b2 = 0.f;
        for (int w = 0; w < 8; w++){ a += sF[w]; b2 += sU[w]; }
        out[UVN + t]        = a  * INV_CNT;   // loss_F
        out[UVN + ITE + t]  = b2 * INV_CNT;   // loss
    }
}

// ---------------- launch ----------------
extern "C" void kernel_launch(void* const* d_in, const int* in_sizes, int n_in,
                              void* d_out, int out_size)
{
    const float* x = (const float*)d_in[0];
    const float* W = (const float*)d_in[1];
    float* out = (float*)d_out;

    k_wsum<<<8192, 256>>>(W);
    k_wred<<<1, 256>>>();
    k_main<<<dim3(CH, B), 256>>>(x, W, out, 0, 1);      // G partials from L0 = x
    for (int t = 0; t < ITE; t++){
        k_eig<<<B, 512>>>();                            // Ur_t from G(L_t)
        k_main<<<dim3(CH, B), 256>>>(x, W, out, t, 0);  // UV_t, losses, L_{t+1}, G(L_{t+1})
        k_loss<<<1, 256>>>(out, t);
    }
}

// round 17
// speedup vs baseline: 1.9469x; 1.1487x over previous
#include <cuda_runtime.h>
#include <cstdint>

#define B   64
#define C   64
#define NN  16384
#define ITE 20
#define RNK 3
#define CH  32                 // G-partial chunks per band
#define CPC (NN/CH)            // 512 cols per chunk
#define SUB 128                // subtile columns
#define NSUBT (CPC/SUB)        // 4
#define NSWEEP 6
#define UVN ((size_t)B*C*NN)   // 67,108,864
#define INV_CNT (1.0f/67108864.0f)   // 2^-26, exact

// ---------------- device scratch (no allocation allowed) ----------------
__device__ float g_L[(size_t)B*C*NN];          // 256 MB  working L
__device__ float g_Gpart[(size_t)CH*B*C*C];    // 32 MB   SYRK partials
__device__ float g_Ur[B*C*RNK];                // top-3 eigvecs per band
__device__ float g_losspart[B*CH*2];           // per-block (lossF, loss)
__device__ float g_wpart[8192];
__device__ float g_rho0;

// ---------------- packed f32x2 helpers (sm_103a) ----------------
__device__ __forceinline__ uint64_t pk2(float a, float b){
    uint64_t r; asm("mov.b64 %0, {%1,%2};" : "=l"(r) : "f"(a), "f"(b)); return r;
}
__device__ __forceinline__ void fma2(uint64_t& acc, uint64_t a, uint64_t b){
    asm("fma.rn.f32x2 %0, %1, %2, %0;" : "+l"(acc) : "l"(a), "l"(b));
}
__device__ __forceinline__ float2 upk2(uint64_t a){
    float2 r; asm("mov.b64 {%0,%1}, %2;" : "=f"(r.x), "=f"(r.y) : "l"(a)); return r;
}

// ---------------- mean(W) ----------------
__global__ void __launch_bounds__(256) k_wsum(const float* __restrict__ W){
    __shared__ float sred[8];
    const int tid = threadIdx.x;
    const size_t base = (size_t)blockIdx.x * 8192;
    float s = 0.f;
    #pragma unroll 4
    for (int k = 0; k < 32; k++) s += W[base + (size_t)k*256 + tid];
    for (int o = 16; o > 0; o >>= 1) s += __shfl_down_sync(0xffffffffu, s, o);
    if ((tid & 31) == 0) sred[tid >> 5] = s;
    __syncthreads();
    if (tid == 0){
        float a = 0.f;
        for (int w = 0; w < 8; w++) a += sred[w];
        g_wpart[blockIdx.x] = a;
    }
}

__global__ void __launch_bounds__(256) k_wred(){
    __shared__ float sred[8];
    const int tid = threadIdx.x;
    float s = 0.f;
    for (int k = 0; k < 32; k++) s += g_wpart[tid + k*256];
    for (int o = 16; o > 0; o >>= 1) s += __shfl_down_sync(0xffffffffu, s, o);
    if ((tid & 31) == 0) sred[tid >> 5] = s;
    __syncthreads();
    if (tid == 0){
        float a = 0.f;
        for (int w = 0; w < 8; w++) a += sred[w];
        g_rho0 = 0.5f * (a * INV_CNT);
    }
}

// ---------------- fused main kernel ----------------
__global__ void __launch_bounds__(256) k_main(const float* __restrict__ x,
                                              const float* __restrict__ W,
                                              float* __restrict__ out,
                                              int t, int init)
{
    __shared__ float Ls[C][132];       // padded stride: av broadcast, bv conflict-free
    __shared__ float cs[RNK][SUB];
    __shared__ float sUr[C*RNK];
    __shared__ float sred[16];

    const int band  = blockIdx.y;
    const int chunk = blockIdx.x;
    const int tid   = threadIdx.x;
    const size_t baseBand = (size_t)band * C * NN;
    const int col0 = chunk * CPC;

    const float* Lsrc = (init || t == 0) ? x : g_L;
    const bool doG  = (init != 0) || (t < ITE-1);
    const bool last = (!init) && (t == ITE-1);

    if (!init && tid < C*RNK) sUr[tid] = g_Ur[band*(C*RNK) + tid];

    float rho = g_rho0;
    for (int i = 0; i < t; i++) rho *= 1.05f;   // replicate f32 repeated multiply

    uint64_t acc2[4][4];
    #pragma unroll
    for (int i = 0; i < 4; i++)
        #pragma unroll
        for (int j = 0; j < 4; j++) acc2[i][j] = pk2(0.f, 0.f);

    float lF = 0.f, lU = 0.f;
    const int tx = tid & 15, ty = tid >> 4;

    for (int s = 0; s < NSUBT; s++) {
        const int nb = col0 + s*SUB;

        // ---- load 64x128 L subtile (float4, coalesced) ----
        {
            const float4* L4 = (const float4*)Lsrc;
            #pragma unroll
            for (int k = 0; k < 8; k++){
                int idx = k*256 + tid;             // 0..2047 float4s
                int ch = idx >> 5, n4 = idx & 31;
                float4 v = L4[(baseBand + (size_t)ch*NN + nb)/4 + n4];
                *(float4*)&Ls[ch][n4*4] = v;
            }
        }
        __syncthreads();

        if (!init) {
            // ---- UtL coefficients: cs[r][n] = sum_ch Ur[ch][r]*L[ch][n] ----
            if (tid < SUB) {
                float c0 = 0.f, c1 = 0.f, c2 = 0.f;
                #pragma unroll
                for (int ch = 0; ch < C; ch++){
                    float l = Ls[ch][tid];
                    c0 += sUr[ch*3+0]*l;
                    c1 += sUr[ch*3+1]*l;
                    c2 += sUr[ch*3+2]*l;
                }
                cs[0][tid] = c0; cs[1][tid] = c1; cs[2][tid] = c2;
            }
            __syncthreads();

            // ---- elementwise: UV, losses, L_new (fast division) ----
            const float4* x4  = (const float4*)x;
            const float4* W4  = (const float4*)W;
            float4* o4  = (float4*)out;
            float4* gl4 = (float4*)g_L;
            #pragma unroll
            for (int k = 0; k < 8; k++){
                int idx = k*256 + tid;
                int ch = idx >> 5, n4 = idx & 31;
                int n = n4*4;
                size_t g4 = (baseBand + (size_t)ch*NN + nb)/4 + n4;
                float4 xv = x4[g4], wv = W4[g4];
                float u0 = sUr[ch*3+0], u1 = sUr[ch*3+1], u2 = sUr[ch*3+2];
                float4 uv;
                uv.x = u0*cs[0][n+0] + u1*cs[1][n+0] + u2*cs[2][n+0];
                uv.y = u0*cs[0][n+1] + u1*cs[1][n+1] + u2*cs[2][n+1];
                uv.z = u0*cs[0][n+2] + u1*cs[1][n+2] + u2*cs[2][n+2];
                uv.w = u0*cs[0][n+3] + u1*cs[1][n+3] + u2*cs[2][n+3];
                lU += uv.x*uv.x + uv.y*uv.y + uv.z*uv.z + uv.w*uv.w;
                float da = uv.x - xv.x, db = uv.y - xv.y;
                float dc = uv.z - xv.z, dd = uv.w - xv.w;
                lF += wv.x*da*da + wv.y*db*db + wv.z*dc*dc + wv.w*dd*dd;
                if (last) {
                    o4[g4] = uv;
                } else {
                    float4 ln;
                    float m;
                    m = __fdividef(rho, wv.x + rho); ln.x = fmaf(m, da, xv.x);
                    m = __fdividef(rho, wv.y + rho); ln.y = fmaf(m, db, xv.y);
                    m = __fdividef(rho, wv.z + rho); ln.z = fmaf(m, dc, xv.z);
                    m = __fdividef(rho, wv.w + rho); ln.w = fmaf(m, dd, xv.w);
                    gl4[g4] = ln;
                    *(float4*)&Ls[ch][n] = ln;   // SYRK uses L_new
                }
            }
            __syncthreads();
        }

        // ---- SYRK accumulate: G += tile * tile^T (f32x2, n-pair packed) ----
        if (doG) {
            #pragma unroll 4
            for (int n = 0; n < SUB; n += 4){
                float4 av[4], bv[4];
                #pragma unroll
                for (int i = 0; i < 4; i++) av[i] = *(const float4*)&Ls[ty+16*i][n];
                #pragma unroll
                for (int j = 0; j < 4; j++) bv[j] = *(const float4*)&Ls[tx+16*j][n];
                uint64_t a01[4], a23[4], b01[4], b23[4];
                #pragma unroll
                for (int i = 0; i < 4; i++){ a01[i] = pk2(av[i].x, av[i].y); a23[i] = pk2(av[i].z, av[i].w); }
                #pragma unroll
                for (int j = 0; j < 4; j++){ b01[j] = pk2(bv[j].x, bv[j].y); b23[j] = pk2(bv[j].z, bv[j].w); }
                #pragma unroll
                for (int i = 0; i < 4; i++)
                    #pragma unroll
                    for (int j = 0; j < 4; j++){
                        fma2(acc2[i][j], a01[i], b01[j]);
                        fma2(acc2[i][j], a23[i], b23[j]);
                    }
            }
        }
        __syncthreads();
    }

    if (doG) {
        float* gp = &g_Gpart[((size_t)chunk*B + band)*(C*C)];
        #pragma unroll
        for (int i = 0; i < 4; i++)
            #pragma unroll
            for (int j = 0; j < 4; j++){
                float2 u = upk2(acc2[i][j]);
                gp[(ty+16*i)*C + (tx+16*j)] = u.x + u.y;
            }
    }

    if (!init) {
        for (int o = 16; o > 0; o >>= 1){
            lF += __shfl_down_sync(0xffffffffu, lF, o);
            lU += __shfl_down_sync(0xffffffffu, lU, o);
        }
        if ((tid & 31) == 0){ sred[tid>>5] = lF; sred[8 + (tid>>5)] = lU; }
        __syncthreads();
        if (tid == 0){
            float a = 0.f, b2 = 0.f;
            for (int w = 0; w < 8; w++){ a += sred[w]; b2 += sred[8+w]; }
            g_losspart[(band*CH + chunk)*2 + 0] = a;
            g_losspart[(band*CH + chunk)*2 + 1] = b2;
        }
    }
}

// ---------------- eigensolver: reduce G partials + parallel Jacobi ----------------
// 512 threads: halves per-thread work in the smem row/col phases (the
// serial-path cost), rotation phase unchanged (tid<32).
__global__ void __launch_bounds__(512) k_eig()
{
    __shared__ float sG[C][65];
    __shared__ float sV[C][65];
    __shared__ float rc[32], rs[32];
    __shared__ int   rp[32], rq[32];
    __shared__ int   topi[RNK];
    const int band = blockIdx.x;
    const int tid  = threadIdx.x;

    for (int e = tid; e < C*C; e += 512){
        float s = 0.f;
        for (int c2 = 0; c2 < CH; c2++)
            s += g_Gpart[((size_t)c2*B + band)*(C*C) + e];
        sG[e>>6][e&63] = s;
        sV[e>>6][e&63] = ((e>>6) == (e&63)) ? 1.f : 0.f;
    }
    __syncthreads();

    for (int sweep = 0; sweep < NSWEEP; sweep++){
        for (int r = 0; r < 63; r++){
            if (tid < 32){
                int p, q;
                if (tid == 0){ p = 63; q = r % 63; }
                else { p = (r + tid) % 63; q = (r + 63 - tid) % 63; }
                if (p > q){ int tmp = p; p = q; q = tmp; }
                float app = sG[p][p], aqq = sG[q][q], apq = sG[p][q];
                float c = 1.f, sn = 0.f;
                // relative guard keeps tau^2 finite for the fast-math path;
                // relatively-tiny apq entries are already converged
                if (fabsf(apq) > 1e-12f*(fabsf(app)+fabsf(aqq)) + 1e-30f){
                    float tau = __fdividef(aqq - app, 2.f * apq);
                    float s1  = 1.f + tau*tau;
                    float sq  = s1 * rsqrtf(s1);            // ~sqrt(1+tau^2)
                    float tt  = __fdividef((tau >= 0.f) ? 1.f : -1.f,
                                           fabsf(tau) + sq);
                    c  = rsqrtf(1.f + tt*tt);
                    sn = tt * c;
                }
                rc[tid] = c; rs[tid] = sn; rp[tid] = p; rq[tid] = q;
            }
            __syncthreads();
            #pragma unroll
            for (int k4 = 0; k4 < 4; k4++){            // rows: G <- J^T G
                int idx = k4*512 + tid;
                int k = idx >> 6, j = idx & 63;
                int p = rp[k], q = rq[k];
                float c = rc[k], sn = rs[k];
                float gp = sG[p][j], gq = sG[q][j];
                sG[p][j] = c*gp - sn*gq;
                sG[q][j] = sn*gp + c*gq;
            }
            __syncthreads();
            #pragma unroll
            for (int k4 = 0; k4 < 4; k4++){            // cols: (.)J  and V <- V J
                int idx = k4*512 + tid;
                int k = idx >> 6, i = idx & 63;
                int p = rp[k], q = rq[k];
                float c = rc[k], sn = rs[k];
                float gp = sG[i][p], gq = sG[i][q];
                sG[i][p] = c*gp - sn*gq;
                sG[i][q] = sn*gp + c*gq;
                float vp = sV[i][p], vq = sV[i][q];
                sV[i][p] = c*vp - sn*vq;
                sV[i][q] = sn*vp + c*vq;
            }
            __syncthreads();
        }
    }

    if (tid == 0){
        unsigned long long used = 0ull;
        for (int rr = 0; rr < RNK; rr++){
            float best = -3.4e38f; int bi = 0;
            for (int i2 = 0; i2 < C; i2++){
                if (used & (1ull << i2)) continue;
                float d = sG[i2][i2];
                if (d > best){ best = d; bi = i2; }
            }
            used |= (1ull << bi);
            topi[rr] = bi;
        }
    }
    __syncthreads();
    for (int idx = tid; idx < C*RNK; idx += 512){
        int ch = idx / 3, rr = idx % 3;
        g_Ur[band*(C*RNK) + idx] = sV[ch][topi[rr]];
    }
}

// ---------------- loss reduction ----------------
__global__ void __launch_bounds__(256) k_loss(float* __restrict__ out, int t){
    __shared__ float sF[8], sU[8];
    const int tid = threadIdx.x;
    float f = 0.f, u = 0.f;
    #pragma unroll
    for (int k = 0; k < 8; k++){
        int idx = tid + k*256;
        f += g_losspart[idx*2 + 0];
        u += g_losspart[idx*2 + 1];
    }
    for (int o = 16; o > 0; o >>= 1){
        f += __shfl_down_sync(0xffffffffu, f, o);
        u += __shfl_down_sync(0xffffffffu, u, o);
    }
    if ((tid & 31) == 0){ sF[tid>>5] = f; sU[tid>>5] = u; }
    __syncthreads();
    if (tid == 0){
        float a = 0.f, b2 = 0.f;
        for (int w = 0; w < 8; w++){ a += sF[w]; b2 += sU[w]; }
        out[UVN + t]        = a  * INV_CNT;   // loss_F
        out[UVN + ITE + t]  = b2 * INV_CNT;   // loss
    }
}

// ---------------- launch ----------------
extern "C" void kernel_launch(void* const* d_in, const int* in_sizes, int n_in,
                              void* d_out, int out_size)
{
    const float* x = (const float*)d_in[0];
    const float* W = (const float*)d_in[1];
    float* out = (float*)d_out;

    k_wsum<<<8192, 256>>>(W);
    k_wred<<<1, 256>>>();
    k_main<<<dim3(CH, B), 256>>>(x, W, out, 0, 1);      // G partials from L0 = x
    for (int t = 0; t < ITE; t++){
        k_eig<<<B, 512>>>();                            // Ur_t from G(L_t)
        k_main<<<dim3(CH, B), 256>>>(x, W, out, t, 0);  // UV_t, losses, L_{t+1}, G(L_{t+1})
        k_loss<<<1, 256>>>(out, t);
    }
}